// round 14
// baseline (speedup 1.0000x reference)
#include <cuda_runtime.h>

// Problem constants (fixed by setup_inputs / module config)
#define B_   8
#define D_   40
#define H_   32
#define W_   88
#define C_   80
#define NPTS (B_ * D_ * H_ * W_)      // 901120
#define HW_  (H_ * W_)                // 2816
#define NX_  256
#define NY_  256
#define NXY_ (NX_ * NY_)              // 65536
#define TMP_ELEMS (B_ * NXY_ * C_)    // 41,943,040 floats = 167.8 MB

// Scratch accumulator in channel-contiguous layout: tmp[b][ix][iy][c]
// (__device__ global array = sanctioned scratch, no runtime allocation)
__device__ __align__(16) float g_tmp[TMP_ELEMS];

// ---------------------------------------------------------------------------
// Kernel 1: zero the scratch accumulator (vectorized stores)
// ---------------------------------------------------------------------------
__global__ void vp_zero_kernel() {
    int i = blockIdx.x * blockDim.x + threadIdx.x;
    float4* p = reinterpret_cast<float4*>(g_tmp);
    if (i < TMP_ELEMS / 4) {
        p[i] = make_float4(0.0f, 0.0f, 0.0f, 0.0f);
    }
}

// ---------------------------------------------------------------------------
// Kernel 2: scatter. One thread per point. Coalesced x reads (consecutive
// threads vary w for a fixed channel), vectorized 128-bit reduction atomics
// into the channel-contiguous scratch (4x fewer RED lanes than scalar).
//
// Index math replicates XLA's lowering of the reference bit-exactly:
// XLA's algebraic simplifier rewrites (g - lo) / dd as (g - lo) * (1/dd),
// and 1/float32(0.4) constant-folds to exactly 2.5f. So the reference
// voxel index is trunc((g + 51.2f) * 2.5f) in round-to-nearest f32.
// ---------------------------------------------------------------------------
__global__ void vp_scatter_kernel(const float* __restrict__ geom,
                                  const float* __restrict__ x) {
    int n = blockIdx.x * blockDim.x + threadIdx.x;
    if (n >= NPTS) return;

    float gx = geom[3 * n + 0];
    float gy = geom[3 * n + 1];
    float gz = geom[3 * n + 2];

    // bounds filter — bitwise-identical to reference float32 comparisons
    bool keep = (gx >= -51.2f) && (gx < 51.2f) &&
                (gy >= -51.2f) && (gy < 51.2f) &&
                (gz >= -10.0f) && (gz < 10.0f);
    if (!keep) return;

    // voxel index: trunc((g + 51.2f) * 2.5f), explicit rn ops so fast-math /
    // contraction can't perturb the rounding; then clip (matches reference)
    int ix = (int)__fmul_rn(__fadd_rn(gx, 51.2f), 2.5f);
    int iy = (int)__fmul_rn(__fadd_rn(gy, 51.2f), 2.5f);
    ix = min(max(ix, 0), NX_ - 1);
    iy = min(max(iy, 0), NY_ - 1);

    // decompose n -> (b, d, h, w), w fastest
    int w = n % W_;
    int t = n / W_;
    int h = t % H_;
    t /= H_;
    int d = t % D_;
    int b = t / D_;

    // x[b][d][c][h][w]: per-channel stride HW_, coalesced across the warp in w
    const float* xp = x + ((b * D_ + d) * C_) * HW_ + h * W_ + w;
    float* dst = g_tmp + (b * NXY_ + (ix << 8) + iy) * C_;

#pragma unroll
    for (int c = 0; c < C_; c += 4) {
        float v0 = xp[(c + 0) * HW_];
        float v1 = xp[(c + 1) * HW_];
        float v2 = xp[(c + 2) * HW_];
        float v3 = xp[(c + 3) * HW_];
        asm volatile("red.global.add.v4.f32 [%0], {%1, %2, %3, %4};"
                     :: "l"(dst + c), "f"(v0), "f"(v1), "f"(v2), "f"(v3)
                     : "memory");
    }
}

// ---------------------------------------------------------------------------
// Kernel 3: transpose tmp[b][p][c] -> out[b][c][p]  (p = ix*NY + iy, 65536)
// Tiled via shared memory, 32 voxels x 80 channels per block.
// Row pitch 81 -> conflict-free strided smem reads in the store phase.
// Fully coalesced: LDG.128 on input, coalesced 32-bit stores on output.
// ---------------------------------------------------------------------------
__global__ void vp_transpose_kernel(float* __restrict__ out) {
    __shared__ float s[32 * 81];

    int tile = blockIdx.x & 2047;       // 65536/32 = 2048 tiles per batch
    int b    = blockIdx.x >> 11;
    int p0   = tile * 32;
    int tid  = threadIdx.x;             // 256 threads

    const float4* src =
        reinterpret_cast<const float4*>(g_tmp + (size_t)(b * NXY_ + p0) * C_);

    // load phase: 32*80 floats = 640 float4, addresses exactly linear in i4
#pragma unroll
    for (int i4 = tid; i4 < 640; i4 += 256) {
        float4 v = src[i4];
        int p = i4 / 20;                 // 20 float4 per voxel row
        int c = (i4 - p * 20) * 4;
        s[p * 81 + c + 0] = v.x;
        s[p * 81 + c + 1] = v.y;
        s[p * 81 + c + 2] = v.z;
        s[p * 81 + c + 3] = v.w;
    }
    __syncthreads();

    // store phase: out[(b*C + c)*NXY + p0 + p], coalesced in p
#pragma unroll
    for (int i = tid; i < 2560; i += 256) {
        int c = i >> 5;
        int p = i & 31;
        out[(b * C_ + c) * NXY_ + p0 + p] = s[p * 81 + c];
    }
}

// ---------------------------------------------------------------------------
// Launch: zero -> scatter -> transpose (all graph-capturable, no allocations)
// ---------------------------------------------------------------------------
extern "C" void kernel_launch(void* const* d_in, const int* in_sizes, int n_in,
                              void* d_out, int out_size) {
    const float* geom = (const float*)d_in[0];   // (8,40,32,88,3) f32
    const float* x    = (const float*)d_in[1];   // (8,40,80,32,88) f32
    float* out        = (float*)d_out;           // (8,80,256,256) f32

    vp_zero_kernel<<<TMP_ELEMS / 4 / 256, 256>>>();
    vp_scatter_kernel<<<(NPTS + 255) / 256, 256>>>(geom, x);
    vp_transpose_kernel<<<B_ * 2048, 256>>>(out);
}

// round 16
// speedup vs baseline: 1.0019x; 1.0019x over previous
#include <cuda_runtime.h>

// Problem constants (fixed by setup_inputs / module config)
#define B_   8
#define D_   40
#define H_   32
#define W_   88
#define C_   80
#define NPTS (B_ * D_ * H_ * W_)      // 901120
#define HW_  (H_ * W_)                // 2816
#define NX_  256
#define NY_  256
#define NXY_ (NX_ * NY_)              // 65536
#define TMP_ELEMS (B_ * NXY_ * C_)    // 41,943,040 floats = 167.8 MB

// Scratch accumulator in channel-contiguous layout: tmp[b][ix][iy][c]
// (__device__ global array = sanctioned scratch, no runtime allocation)
__device__ __align__(16) float g_tmp[TMP_ELEMS];

// ---------------------------------------------------------------------------
// Kernel 1: zero the scratch accumulator (vectorized stores)
// ---------------------------------------------------------------------------
__global__ void vp_zero_kernel() {
    int i = blockIdx.x * blockDim.x + threadIdx.x;
    float4* p = reinterpret_cast<float4*>(g_tmp);
    if (i < TMP_ELEMS / 4) {
        p[i] = make_float4(0.0f, 0.0f, 0.0f, 0.0f);
    }
}

// ---------------------------------------------------------------------------
// Kernel 2: scatter. One thread per point. Coalesced x reads (consecutive
// threads vary w for a fixed channel), vectorized 128-bit reduction atomics
// into the channel-contiguous scratch (4x fewer RED lanes than scalar).
//
// Index math replicates XLA's lowering of the reference bit-exactly:
// XLA's algebraic simplifier rewrites (g - lo) / dd as (g - lo) * (1/dd),
// and 1/float32(0.4) constant-folds to exactly 2.5f. So the reference
// voxel index is trunc((g + 51.2f) * 2.5f) in round-to-nearest f32.
// ---------------------------------------------------------------------------
__global__ void vp_scatter_kernel(const float* __restrict__ geom,
                                  const float* __restrict__ x) {
    int n = blockIdx.x * blockDim.x + threadIdx.x;
    if (n >= NPTS) return;

    float gx = geom[3 * n + 0];
    float gy = geom[3 * n + 1];
    float gz = geom[3 * n + 2];

    // bounds filter — bitwise-identical to reference float32 comparisons
    bool keep = (gx >= -51.2f) && (gx < 51.2f) &&
                (gy >= -51.2f) && (gy < 51.2f) &&
                (gz >= -10.0f) && (gz < 10.0f);
    if (!keep) return;

    // voxel index: trunc((g + 51.2f) * 2.5f), explicit rn ops so fast-math /
    // contraction can't perturb the rounding; then clip (matches reference)
    int ix = (int)__fmul_rn(__fadd_rn(gx, 51.2f), 2.5f);
    int iy = (int)__fmul_rn(__fadd_rn(gy, 51.2f), 2.5f);
    ix = min(max(ix, 0), NX_ - 1);
    iy = min(max(iy, 0), NY_ - 1);

    // decompose n -> (b, d, h, w), w fastest
    int w = n % W_;
    int t = n / W_;
    int h = t % H_;
    t /= H_;
    int d = t % D_;
    int b = t / D_;

    // x[b][d][c][h][w]: per-channel stride HW_, coalesced across the warp in w
    const float* xp = x + ((b * D_ + d) * C_) * HW_ + h * W_ + w;
    float* dst = g_tmp + (b * NXY_ + (ix << 8) + iy) * C_;

#pragma unroll
    for (int c = 0; c < C_; c += 4) {
        float v0 = xp[(c + 0) * HW_];
        float v1 = xp[(c + 1) * HW_];
        float v2 = xp[(c + 2) * HW_];
        float v3 = xp[(c + 3) * HW_];
        asm volatile("red.global.add.v4.f32 [%0], {%1, %2, %3, %4};"
                     :: "l"(dst + c), "f"(v0), "f"(v1), "f"(v2), "f"(v3)
                     : "memory");
    }
}

// ---------------------------------------------------------------------------
// Kernel 3: transpose tmp[b][p][c] -> out[b][c][p]  (p = ix*NY + iy, 65536)
// Tiled via shared memory, 32 voxels x 80 channels per block.
// Row pitch 81 -> conflict-free strided smem reads in the store phase.
// Fully coalesced: LDG.128 on input, coalesced 32-bit stores on output.
// ---------------------------------------------------------------------------
__global__ void vp_transpose_kernel(float* __restrict__ out) {
    __shared__ float s[32 * 81];

    int tile = blockIdx.x & 2047;       // 65536/32 = 2048 tiles per batch
    int b    = blockIdx.x >> 11;
    int p0   = tile * 32;
    int tid  = threadIdx.x;             // 256 threads

    const float4* src =
        reinterpret_cast<const float4*>(g_tmp + (size_t)(b * NXY_ + p0) * C_);

    // load phase: 32*80 floats = 640 float4, addresses exactly linear in i4
#pragma unroll
    for (int i4 = tid; i4 < 640; i4 += 256) {
        float4 v = src[i4];
        int p = i4 / 20;                 // 20 float4 per voxel row
        int c = (i4 - p * 20) * 4;
        s[p * 81 + c + 0] = v.x;
        s[p * 81 + c + 1] = v.y;
        s[p * 81 + c + 2] = v.z;
        s[p * 81 + c + 3] = v.w;
    }
    __syncthreads();

    // store phase: out[(b*C + c)*NXY + p0 + p], coalesced in p
#pragma unroll
    for (int i = tid; i < 2560; i += 256) {
        int c = i >> 5;
        int p = i & 31;
        out[(b * C_ + c) * NXY_ + p0 + p] = s[p * 81 + c];
    }
}

// ---------------------------------------------------------------------------
// Launch: zero -> scatter -> transpose (all graph-capturable, no allocations)
// ---------------------------------------------------------------------------
extern "C" void kernel_launch(void* const* d_in, const int* in_sizes, int n_in,
                              void* d_out, int out_size) {
    const float* geom = (const float*)d_in[0];   // (8,40,32,88,3) f32
    const float* x    = (const float*)d_in[1];   // (8,40,80,32,88) f32
    float* out        = (float*)d_out;           // (8,80,256,256) f32

    vp_zero_kernel<<<TMP_ELEMS / 4 / 256, 256>>>();
    vp_scatter_kernel<<<(NPTS + 255) / 256, 256>>>(geom, x);
    vp_transpose_kernel<<<B_ * 2048, 256>>>(out);
}